// round 4
// baseline (speedup 1.0000x reference)
#include <cuda_runtime.h>
#include <math.h>
#include <stdint.h>

// Problem constants
#define BB     32
#define LL     4096
#define DIN    150
#define DST    75
#define HID    75
#define HIDP   80        // padded hidden (W1 pad = 0)
#define K2N    75        // DIN/2 k-pairs
#define TILE_L 128
#define NCHUNK (LL / TILE_L)   // 32
#define XSTR   152       // x smem row stride (floats), even for float2 reads
#define NTH    256       // kernel2 threads (16x16)
#define RTH    320       // k_reduce threads (2 stripes x 160)

// scratch: state projection + b0, padded to HIDP
__device__ float g_spb[BB * HIDP];
// mask dtype flag: 1 = int32, 0 = int8/bool bytes
__device__ int g_mask_i32;
// partial weighted sums and exp-sums (deterministic two-stage reduction)
__device__ float g_part[BB][NCHUNK][160];
__device__ float g_psum[BB][NCHUNK];

// ---------------------------------------------------------------------------
// Kernel 0: detect mask dtype (int8 bool seen as int32 is in {0,1} w.p. ~0)
// ---------------------------------------------------------------------------
__global__ void k_detect_mask(const int* __restrict__ m) {
    int i32 = 1;
    for (int i = 0; i < 64; ++i) {
        int v = m[i];
        if (v != 0 && v != 1) { i32 = 0; break; }
    }
    g_mask_i32 = i32;
}

// ---------------------------------------------------------------------------
// Kernel 1: spb[b][j] = b0[j] + state[b] . W0[0:75, j]
// ---------------------------------------------------------------------------
__global__ void k_stateproj(const float* __restrict__ state,
                            const float* __restrict__ W0,
                            const float* __restrict__ b0) {
    int b = blockIdx.x;
    int j = threadIdx.x;               // 0..HIDP-1
    float acc = 0.0f;
    if (j < HID) {
        acc = b0[j];
        const float* st = state + b * DST;
#pragma unroll 5
        for (int k = 0; k < DST; ++k)
            acc = fmaf(st[k], W0[k * HID + j], acc);
    }
    g_spb[b * HIDP + j] = acc;
}

// packed fp32x2 FMA (Blackwell FFMA2 — PTX-only path)
__device__ __forceinline__ void ffma2(unsigned long long& d,
                                      unsigned long long a,
                                      unsigned long long b) {
    asm("fma.rn.f32x2 %0, %1, %2, %0;" : "+l"(d) : "l"(a), "l"(b));
}

// ---------------------------------------------------------------------------
// Kernel 2 (exact R2 version — measured at FFMA2 floor ~43us):
// scores. For each row l: h = tanh(x.W0in + spb); s = h.W1 + b1;
// s1 = s - 1e30*(1-mask). Register-tiled GEMM, FFMA2-packed over k-pairs.
// ---------------------------------------------------------------------------
__global__ __launch_bounds__(NTH, 1)
void k_scores(const float* __restrict__ inputs,
              const float* __restrict__ W0,
              const float* __restrict__ W1,
              const float* __restrict__ b1,
              const void* __restrict__ cmask,
              float* __restrict__ s1_out) {
    extern __shared__ float sm[];
    float* xs = sm;                                        // [TILE_L][XSTR]
    float2* ws2 = (float2*)(sm + TILE_L * XSTR);           // [K2N][HIDP] k-pairs
    float* spb_s = (float*)(ws2 + K2N * HIDP);             // [HIDP]
    float* w1s   = spb_s + HIDP;                           // [HIDP]

    const int b   = blockIdx.y;
    const int l0  = blockIdx.x * TILE_L;
    const int tid = threadIdx.x;

    // --- stage input tile (coalesced float2 reads, conflict-free STS) ---
    {
        const float2* gin = (const float2*)(inputs + ((size_t)b * LL + l0) * DIN);
        for (int idx = tid; idx < TILE_L * K2N; idx += NTH) {
            int r  = idx / K2N;
            int k2 = idx - r * K2N;
            float2 v = gin[(size_t)r * K2N + k2];
            *(float2*)&xs[r * XSTR + 2 * k2] = v;
        }
    }
    // --- stage W0 input-part, repacked as k-pairs ---
    for (int idx = tid; idx < K2N * HIDP; idx += NTH) {
        int k2 = idx / HIDP;
        int j  = idx - k2 * HIDP;
        float2 w;
        if (j < HID) {
            w.x = W0[(DST + 2 * k2)     * HID + j];
            w.y = W0[(DST + 2 * k2 + 1) * HID + j];
        } else { w.x = 0.0f; w.y = 0.0f; }
        ws2[idx] = w;
    }
    if (tid < HIDP) {
        spb_s[tid] = g_spb[b * HIDP + tid];
        w1s[tid]   = (tid < HID) ? W1[tid] : 0.0f;
    }
    __syncthreads();

    const int tx = tid & 15;          // col group: cols tx*5 .. tx*5+4
    const int ty = tid >> 4;          // row group: rows ty + 16*i, i<8

    unsigned long long acc[8][5];
#pragma unroll
    for (int i = 0; i < 8; ++i)
#pragma unroll
        for (int c = 0; c < 5; ++c) acc[i][c] = 0ULL;

    const unsigned long long* wrow = (const unsigned long long*)ws2 + tx * 5;

#pragma unroll 3
    for (int k2 = 0; k2 < K2N; ++k2) {
        unsigned long long xv[8], wv[5];
#pragma unroll
        for (int i = 0; i < 8; ++i)
            xv[i] = *(const unsigned long long*)&xs[(ty + 16 * i) * XSTR + 2 * k2];
#pragma unroll
        for (int c = 0; c < 5; ++c)
            wv[c] = wrow[(size_t)k2 * HIDP + c];
#pragma unroll
        for (int i = 0; i < 8; ++i)
#pragma unroll
            for (int c = 0; c < 5; ++c)
                ffma2(acc[i][c], xv[i], wv[c]);
    }

    // --- epilogue: tanh + dot(W1) + 16-lane reduce + mask ---
    float w1c[5], spc[5];
#pragma unroll
    for (int c = 0; c < 5; ++c) {
        int j = tx * 5 + c;
        w1c[c] = w1s[j];
        spc[c] = spb_s[j];
    }
    const float b1v = b1[0];
    const int mask_i32 = g_mask_i32;

#pragma unroll
    for (int i = 0; i < 8; ++i) {
        float s = 0.0f;
#pragma unroll
        for (int c = 0; c < 5; ++c) {
            unsigned long long a = acc[i][c];
            float lo = __uint_as_float((unsigned)(a & 0xffffffffu));
            float hi = __uint_as_float((unsigned)(a >> 32));
            float h  = lo + hi + spc[c];
            s = fmaf(tanhf(h), w1c[c], s);
        }
        s += __shfl_xor_sync(0xffffffffu, s, 1);
        s += __shfl_xor_sync(0xffffffffu, s, 2);
        s += __shfl_xor_sync(0xffffffffu, s, 4);
        s += __shfl_xor_sync(0xffffffffu, s, 8);
        if (tx == 0) {
            size_t idx = (size_t)b * LL + l0 + ty + 16 * i;
            int mv = mask_i32 ? ((const int*)cmask)[idx]
                              : (int)((const unsigned char*)cmask)[idx];
            float sv = s + b1v;
            if (mv == 0) sv -= 1e30f;
            s1_out[idx] = sv;
        }
    }
}

// ---------------------------------------------------------------------------
// Kernel R: per-(b,chunk) softmax-numerator partials. No max pass needed:
// |s| <= ~8 (tanh-bounded), masked entries are exactly -1e30 -> exp = 0.
// partial[f] = sum_{r in tile} exp(s1[r]) * x[r][f];  psum = sum exp(s1[r]).
// ---------------------------------------------------------------------------
__global__ __launch_bounds__(RTH)
void k_reduce(const float* __restrict__ inputs,
              const float* __restrict__ s1) {
    __shared__ float es[TILE_L];
    __shared__ float pstr[2][160];
    __shared__ float psred[4];

    const int b     = blockIdx.y;
    const int chunk = blockIdx.x;
    const int l0    = chunk * TILE_L;
    const int tid   = threadIdx.x;

    if (tid < TILE_L)
        es[tid] = __expf(s1[(size_t)b * LL + l0 + tid]);
    __syncthreads();

    const int stripe = tid / 160;      // 0 or 1
    const int f      = tid - stripe * 160;
    if (f < DIN) {
        const float* xb = inputs + ((size_t)b * LL + l0) * DIN + f;
        float acc = 0.0f;
#pragma unroll 8
        for (int r = stripe; r < TILE_L; r += 2)
            acc = fmaf(es[r], xb[(size_t)r * DIN], acc);
        pstr[stripe][f] = acc;
    } else {
        pstr[stripe][f] = 0.0f;
    }

    // exp-sum via 4 warp reductions of es
    if (tid < TILE_L) {
        float v = es[tid];
        v += __shfl_xor_sync(0xffffffffu, v, 16);
        v += __shfl_xor_sync(0xffffffffu, v, 8);
        v += __shfl_xor_sync(0xffffffffu, v, 4);
        v += __shfl_xor_sync(0xffffffffu, v, 2);
        v += __shfl_xor_sync(0xffffffffu, v, 1);
        if ((tid & 31) == 0) psred[tid >> 5] = v;
    }
    __syncthreads();

    if (tid < 160)
        g_part[b][chunk][tid] = pstr[0][tid] + pstr[1][tid];
    if (tid == 0)
        g_psum[b][chunk] = (psred[0] + psred[1]) + (psred[2] + psred[3]);
}

// ---------------------------------------------------------------------------
// Kernel 3: finish — res[b][f] = sum_c part[b][c][f] / sum_c psum[b][c]
// ---------------------------------------------------------------------------
__global__ void k_finish(float* __restrict__ res) {
    const int b = blockIdx.x;
    const int f = threadIdx.x;         // 0..149
    float tot = 0.0f;
#pragma unroll
    for (int c = 0; c < NCHUNK; ++c) tot += g_psum[b][c];
    float p = 0.0f;
#pragma unroll
    for (int c = 0; c < NCHUNK; ++c) p += g_part[b][c][f];
    res[b * DIN + f] = p / tot;
}

// ---------------------------------------------------------------------------
extern "C" void kernel_launch(void* const* d_in, const int* in_sizes, int n_in,
                              void* d_out, int out_size) {
    const float* inputs = (const float*)d_in[0];
    const float* state  = (const float*)d_in[1];
    const void*  cmask  = d_in[2];
    const float* W0     = (const float*)d_in[3];
    const float* b0     = (const float*)d_in[4];
    const float* W1     = (const float*)d_in[5];
    const float* b1     = (const float*)d_in[6];

    float* out = (float*)d_out;
    float* res = out;                 // [B][1][DIN] = 4800 floats
    float* s1  = out + BB * DIN;      // [B][L]      = 131072 floats

    const int smem2 = (TILE_L * XSTR + K2N * HIDP * 2 + 2 * HIDP)
                      * (int)sizeof(float);
    cudaFuncSetAttribute(k_scores, cudaFuncAttributeMaxDynamicSharedMemorySize, smem2);

    k_detect_mask<<<1, 1>>>((const int*)cmask);
    k_stateproj<<<BB, HIDP>>>(state, W0, b0);

    dim3 g2(NCHUNK, BB);
    k_scores<<<g2, NTH, smem2>>>(inputs, W0, W1, b1, cmask, s1);

    k_reduce<<<g2, RTH>>>(inputs, s1);
    k_finish<<<BB, DIN>>>(res);
}

// round 6
// speedup vs baseline: 1.1886x; 1.1886x over previous
#include <cuda_runtime.h>
#include <math.h>
#include <stdint.h>

// Problem constants
#define BB     32
#define LL     4096
#define DIN    150
#define DST    75
#define HID    75
#define HIDP   80        // padded hidden (W1 pad = 0)
#define K2N    75        // DIN/2 k-pairs
#define TILE_L 128
#define NCHUNK (LL / TILE_L)   // 32
#define XT_STR 130       // xs_t row stride in float2 units (EVEN -> 16B-aligned rows)
#define NTH    256       // kernel2 threads (16 tx x 16 ty)

typedef unsigned long long ull;

// scratch: state projection + b0, padded to HIDP
__device__ float g_spb[BB * HIDP];
// partial weighted sums and exp-sums (deterministic two-stage reduction)
__device__ float g_part[BB][NCHUNK][160];
__device__ float g_psum[BB][NCHUNK];

// ---------------------------------------------------------------------------
// Kernel 1: spb[b][j] = b0[j] + state[b] . W0[0:75, j]
// ---------------------------------------------------------------------------
__global__ void k_stateproj(const float* __restrict__ state,
                            const float* __restrict__ W0,
                            const float* __restrict__ b0) {
    int b = blockIdx.x;
    int j = threadIdx.x;               // 0..HIDP-1
    float acc = 0.0f;
    if (j < HID) {
        acc = b0[j];
        const float* st = state + b * DST;
#pragma unroll 5
        for (int k = 0; k < DST; ++k)
            acc = fmaf(st[k], W0[k * HID + j], acc);
    }
    g_spb[b * HIDP + j] = acc;
}

// packed fp32x2 FMA (Blackwell FFMA2 — PTX-only path)
__device__ __forceinline__ void ffma2(ull& d, ull a, ull b) {
    asm("fma.rn.f32x2 %0, %1, %2, %0;" : "+l"(d) : "l"(a), "l"(b));
}

// ---------------------------------------------------------------------------
// Kernel 2: fused scores + softmax-numerator partials.
// x tile stored TRANSPOSED as xs_t[k2][row] (float2 = k-pair per cell): main
// loop reads xv as 4 x LDS.128 broadcasts (rows 8-aligned, stride even).
// wv: 5 scalar LDS.64, banks tx*10 mod 32 all-distinct -> conflict-free.
// ---------------------------------------------------------------------------
__global__ __launch_bounds__(NTH, 1)
void k_scores(const float* __restrict__ inputs,
              const float* __restrict__ W0,
              const float* __restrict__ W1,
              const float* __restrict__ b1,
              const int* __restrict__ cmask,
              float* __restrict__ s1_out) {
    extern __shared__ float sm[];
    float* xs_t = sm;                                      // [K2N][XT_STR] float2
    float2* ws2 = (float2*)(sm + K2N * XT_STR * 2);        // [K2N][HIDP] k-pairs
    float* spb_s = (float*)(ws2 + K2N * HIDP);             // [HIDP]
    float* w1s   = spb_s + HIDP;                           // [HIDP]
    float* es    = w1s + HIDP;                             // [TILE_L]
    float* psred = es + TILE_L;                            // [4]

    const int b     = blockIdx.y;
    const int chunk = blockIdx.x;
    const int l0    = chunk * TILE_L;
    const int tid   = threadIdx.x;

    // --- stage input tile transposed: xs_t[k2][r] = (x[r][2k2], x[r][2k2+1])
    {
        const float2* gin = (const float2*)(inputs + ((size_t)b * LL + l0) * DIN);
        float2* xt2 = (float2*)xs_t;
        for (int idx = tid; idx < K2N * TILE_L; idx += NTH) {
            int r  = idx & (TILE_L - 1);
            int k2 = idx >> 7;
            xt2[k2 * XT_STR + r] = gin[(size_t)r * K2N + k2];
        }
    }
    // --- stage W0 input-part, repacked as k-pairs ---
    for (int idx = tid; idx < K2N * HIDP; idx += NTH) {
        int k2 = idx / HIDP;
        int j  = idx - k2 * HIDP;
        float2 w;
        if (j < HID) {
            w.x = W0[(DST + 2 * k2)     * HID + j];
            w.y = W0[(DST + 2 * k2 + 1) * HID + j];
        } else { w.x = 0.0f; w.y = 0.0f; }
        ws2[idx] = w;
    }
    if (tid < HIDP) {
        spb_s[tid] = g_spb[b * HIDP + tid];
        w1s[tid]   = (tid < HID) ? W1[tid] : 0.0f;
    }
    __syncthreads();

    const int tx = tid & 15;          // col group: cols tx*5 .. tx*5+4
    const int ty = tid >> 4;          // row group: rows ty*8 .. ty*8+7
    const int r0 = ty * 8;

    ull acc[8][5];
#pragma unroll
    for (int i = 0; i < 8; ++i)
#pragma unroll
        for (int c = 0; c < 5; ++c) acc[i][c] = 0ULL;

    const ull* xbase = (const ull*)xs_t + r0;        // + k2*XT_STR (even)
    const ull* wbase = (const ull*)ws2 + tx * 5;     // + k2*HIDP

#pragma unroll 5
    for (int k2 = 0; k2 < K2N; ++k2) {
        // 8 consecutive float2 rows -> 4 x 16B aligned vector loads (broadcast)
        const ull* xr = xbase + (size_t)k2 * XT_STR;
        ulonglong2 xv01 = *(const ulonglong2*)(xr);
        ulonglong2 xv23 = *(const ulonglong2*)(xr + 2);
        ulonglong2 xv45 = *(const ulonglong2*)(xr + 4);
        ulonglong2 xv67 = *(const ulonglong2*)(xr + 6);
        ull xv[8] = { xv01.x, xv01.y, xv23.x, xv23.y,
                      xv45.x, xv45.y, xv67.x, xv67.y };
        // 5 scalar 8B loads, conflict-free across tx
        const ull* wr = wbase + (size_t)k2 * HIDP;
        ull wv[5] = { wr[0], wr[1], wr[2], wr[3], wr[4] };
#pragma unroll
        for (int i = 0; i < 8; ++i)
#pragma unroll
            for (int c = 0; c < 5; ++c)
                ffma2(acc[i][c], xv[i], wv[c]);
    }

    // --- epilogue: tanh + dot(W1) + 16-lane reduce + mask + exp ---
    float w1c[5], spc[5];
#pragma unroll
    for (int c = 0; c < 5; ++c) {
        int j = tx * 5 + c;
        w1c[c] = w1s[j];
        spc[c] = spb_s[j];
    }
    const float b1v = b1[0];

#pragma unroll
    for (int i = 0; i < 8; ++i) {
        float s = 0.0f;
#pragma unroll
        for (int c = 0; c < 5; ++c) {
            ull a = acc[i][c];
            float lo = __uint_as_float((unsigned)(a & 0xffffffffu));
            float hi = __uint_as_float((unsigned)(a >> 32));
            float h  = lo + hi + spc[c];
            s = fmaf(tanhf(h), w1c[c], s);
        }
        s += __shfl_xor_sync(0xffffffffu, s, 1);
        s += __shfl_xor_sync(0xffffffffu, s, 2);
        s += __shfl_xor_sync(0xffffffffu, s, 4);
        s += __shfl_xor_sync(0xffffffffu, s, 8);
        if (tx == 0) {
            int r = r0 + i;
            size_t idx = (size_t)b * LL + l0 + r;
            float sv = s + b1v;
            if (cmask[idx] == 0) sv -= 1e30f;
            s1_out[idx] = sv;
            es[r] = expf(sv);          // masked -> exp(-1e30) = 0
        }
    }
    __syncthreads();

    // --- fused weighted partial sum from resident transposed tile ---
    if (tid < DIN) {
        const int f2   = tid >> 1;     // float2 index
        const int comp = tid & 1;
        const float* xcol = xs_t + (size_t)f2 * (XT_STR * 2) + comp;
        float p = 0.0f;
#pragma unroll 8
        for (int r = 0; r < TILE_L; ++r)
            p = fmaf(es[r], xcol[2 * r], p);
        g_part[b][chunk][tid] = p;
    } else if (tid < 160) {
        g_part[b][chunk][tid] = 0.0f;
    }
    // exp-sum: 4 warps cover the 128 rows
    if (tid < TILE_L) {
        float v = es[tid];
        v += __shfl_xor_sync(0xffffffffu, v, 16);
        v += __shfl_xor_sync(0xffffffffu, v, 8);
        v += __shfl_xor_sync(0xffffffffu, v, 4);
        v += __shfl_xor_sync(0xffffffffu, v, 2);
        v += __shfl_xor_sync(0xffffffffu, v, 1);
        if ((tid & 31) == 0) psred[tid >> 5] = v;
    }
    __syncthreads();
    if (tid == 0)
        g_psum[b][chunk] = (psred[0] + psred[1]) + (psred[2] + psred[3]);
}

// ---------------------------------------------------------------------------
// Kernel 3: finish — res[b][f] = sum_c part[b][c][f] / sum_c psum[b][c]
// ---------------------------------------------------------------------------
__global__ void k_finish(float* __restrict__ res) {
    const int b = blockIdx.x;
    const int f = threadIdx.x;         // 0..149
    float tot = 0.0f;
#pragma unroll
    for (int c = 0; c < NCHUNK; ++c) tot += g_psum[b][c];
    float p = 0.0f;
#pragma unroll
    for (int c = 0; c < NCHUNK; ++c) p += g_part[b][c][f];
    res[b * DIN + f] = p / tot;
}

// ---------------------------------------------------------------------------
extern "C" void kernel_launch(void* const* d_in, const int* in_sizes, int n_in,
                              void* d_out, int out_size) {
    const float* inputs = (const float*)d_in[0];
    const float* state  = (const float*)d_in[1];
    const int*   cmask  = (const int*)d_in[2];   // bool transported as int32 (verified R2)
    const float* W0     = (const float*)d_in[3];
    const float* b0     = (const float*)d_in[4];
    const float* W1     = (const float*)d_in[5];
    const float* b1     = (const float*)d_in[6];

    float* out = (float*)d_out;
    float* res = out;                 // [B][1][DIN] = 4800 floats
    float* s1  = out + BB * DIN;      // [B][L]      = 131072 floats

    const int smem2 = (K2N * XT_STR * 2 + K2N * HIDP * 2 + 2 * HIDP + TILE_L + 8)
                      * (int)sizeof(float);
    cudaFuncSetAttribute(k_scores, cudaFuncAttributeMaxDynamicSharedMemorySize, smem2);

    k_stateproj<<<BB, HIDP>>>(state, W0, b0);

    dim3 g2(NCHUNK, BB);
    k_scores<<<g2, NTH, smem2>>>(inputs, W0, W1, b1, cmask, s1);

    k_finish<<<BB, DIN>>>(res);
}